// round 1
// baseline (speedup 1.0000x reference)
#include <cuda_runtime.h>
#include <cstdint>
#include <math.h>

// ---------------- fixed problem shapes ----------------
#define N_TOK   32760          // N_t * N_h * N_w = 21*30*52
#define DIM     1536
#define NHEADS  12
#define HD      128
#define S_SP    1560           // 30*52
#define N_T     21
#define ENC     768
#define NA      32
#define KV_ROWS 672            // N_t * NA
#define LOG2_10000 13.287712379549449f

// ---------------- scratch (device globals; no runtime alloc) ----------------
__device__ float g_q[N_TOK * DIM];          // 201 MB
__device__ float g_attn[N_TOK * DIM];       // 201 MB
__device__ float g_kv[KV_ROWS * 2 * DIM];   // 8.3 MB
__device__ float g_k[KV_ROWS * DIM];        // 4.1 MB
__device__ float g_v[KV_ROWS * DIM];        // 4.1 MB
__device__ float g_pos[N_TOK];
__device__ float g_mm[4];                   // min0,max0,min1,max1

// ---------------- 1) min/max of the two attn-map rows ----------------
__global__ void minmax_kernel(const float* __restrict__ m) {
    __shared__ float s0[256], s1[256], s2[256], s3[256];
    int tid = threadIdx.x;
    float mn0 = 1e30f, mx0 = -1e30f, mn1 = 1e30f, mx1 = -1e30f;
    for (int i = tid; i < N_TOK; i += 256) {
        float v0 = m[i], v1 = m[N_TOK + i];
        mn0 = fminf(mn0, v0); mx0 = fmaxf(mx0, v0);
        mn1 = fminf(mn1, v1); mx1 = fmaxf(mx1, v1);
    }
    s0[tid] = mn0; s1[tid] = mx0; s2[tid] = mn1; s3[tid] = mx1;
    __syncthreads();
    for (int off = 128; off > 0; off >>= 1) {
        if (tid < off) {
            s0[tid] = fminf(s0[tid], s0[tid + off]);
            s1[tid] = fmaxf(s1[tid], s1[tid + off]);
            s2[tid] = fminf(s2[tid], s2[tid + off]);
            s3[tid] = fmaxf(s3[tid], s3[tid + off]);
        }
        __syncthreads();
    }
    if (tid == 0) { g_mm[0] = s0[0]; g_mm[1] = s1[0]; g_mm[2] = s2[0]; g_mm[3] = s3[0]; }
}

// ---------------- 2) per-token rotary position (speaker routing) ----------------
__global__ void pos_kernel(const float* __restrict__ m) {
    int n = blockIdx.x * blockDim.x + threadIdx.x;
    if (n >= N_TOK) return;
    float m0 = m[n], m1 = m[N_TOK + n];
    float r;
    if (m0 >= m1) {   // argmax==0 (first-max tie rule)
        r = (m0 - g_mm[0]) / (g_mm[1] - g_mm[0] + 1e-8f) * 4.0f;            // [0,4]
    } else {
        r = (m1 - g_mm[2]) / (g_mm[3] - g_mm[2] + 1e-8f) * 4.0f + 20.0f;    // [20,24]
    }
    g_pos[n] = r;
}

// ---------------- generic GEMM:  C[M,N] = A[M,K] * B[N,K]^T + bias[N] ----------------
// classic 128x128x8 tiling, 256 threads, 8x8 microtile (fp32)
__global__ void __launch_bounds__(256) gemm_nt_bias(
    const float* __restrict__ A, const float* __restrict__ B,
    const float* __restrict__ bias, float* __restrict__ C,
    int M, int N, int K)
{
    __shared__ float As[8][128];
    __shared__ float Bs[8][128];
    const int tid  = threadIdx.x;
    const int row0 = blockIdx.y * 128;
    const int col0 = blockIdx.x * 128;
    const int tx = tid & 15;       // 16 col threads
    const int ty = tid >> 4;       // 16 row threads
    const int lr = tid >> 1;       // load row within tile (0..127)
    const int lc = (tid & 1) * 4;  // load col within tile (0 or 4)

    float acc[8][8];
#pragma unroll
    for (int i = 0; i < 8; i++)
#pragma unroll
        for (int j = 0; j < 8; j++) acc[i][j] = 0.0f;

    const bool arow_ok = (row0 + lr) < M;   // N,K are multiples of 128/8 in all our calls
    const float* Ap = A + (size_t)(row0 + lr) * K + lc;
    const float* Bp = B + (size_t)(col0 + lr) * K + lc;

    for (int k0 = 0; k0 < K; k0 += 8) {
        float4 av = arow_ok ? *(const float4*)(Ap + k0) : make_float4(0.f, 0.f, 0.f, 0.f);
        float4 bv = *(const float4*)(Bp + k0);
        As[lc + 0][lr] = av.x; As[lc + 1][lr] = av.y; As[lc + 2][lr] = av.z; As[lc + 3][lr] = av.w;
        Bs[lc + 0][lr] = bv.x; Bs[lc + 1][lr] = bv.y; Bs[lc + 2][lr] = bv.z; Bs[lc + 3][lr] = bv.w;
        __syncthreads();
#pragma unroll
        for (int k = 0; k < 8; k++) {
            float a[8], b[8];
#pragma unroll
            for (int i = 0; i < 8; i++) a[i] = As[k][ty * 8 + i];
#pragma unroll
            for (int j = 0; j < 8; j++) b[j] = Bs[k][tx * 8 + j];
#pragma unroll
            for (int i = 0; i < 8; i++)
#pragma unroll
                for (int j = 0; j < 8; j++)
                    acc[i][j] += a[i] * b[j];
        }
        __syncthreads();
    }

#pragma unroll
    for (int i = 0; i < 8; i++) {
        int r = row0 + ty * 8 + i;
        if (r < M) {
            float* Cp = C + (size_t)r * N + col0 + tx * 8;
            const float* bp = bias + col0 + tx * 8;
#pragma unroll
            for (int j = 0; j < 8; j++)
                Cp[j] = acc[i][j] + bp[j];
        }
    }
}

// ---------------- 4) interleaved RoPE on q (per-token position) ----------------
// one thread per (token, pair): total N_TOK * 768
__global__ void rope_q_kernel() {
    int idx = blockIdx.x * blockDim.x + threadIdx.x;
    if (idx >= N_TOK * (DIM / 2)) return;
    int n = idx / (DIM / 2);
    int p = idx - n * (DIM / 2);         // pair index within the 1536-dim row
    int i = p & 63;                       // pair index within a 128-d head
    float fr = exp2f(-(float)i * (LOG2_10000 / 64.0f));   // 10000^(-i/64)
    float th = g_pos[n] * fr;
    float s, c;
    sincosf(th, &s, &c);
    float* base = g_q + (size_t)n * DIM + 2 * p;
    float a = base[0], b = base[1];
    base[0] = a * c - b * s;
    base[1] = b * c + a * s;
}

// ---------------- 6) split kv -> k (with bucket-centre RoPE) and v ----------------
// one thread per (kv_row, pair): total 672 * 768
__global__ void rope_k_split_kernel() {
    int idx = blockIdx.x * blockDim.x + threadIdx.x;
    if (idx >= KV_ROWS * (DIM / 2)) return;
    int r = idx / (DIM / 2);
    int p = idx - r * (DIM / 2);
    int a = r & 31;                       // audio-token index within frame
    float pos = (a < 16) ? 2.0f : 22.0f;  // bucket centres
    int i = p & 63;
    float fr = exp2f(-(float)i * (LOG2_10000 / 64.0f));
    float th = pos * fr;
    float s, c;
    sincosf(th, &s, &c);
    const float* kvr = g_kv + (size_t)r * (2 * DIM);
    float ka = kvr[2 * p], kb = kvr[2 * p + 1];
    size_t o = (size_t)r * DIM + 2 * p;
    g_k[o]     = ka * c - kb * s;
    g_k[o + 1] = kb * c + ka * s;
    g_v[o]     = kvr[DIM + 2 * p];
    g_v[o + 1] = kvr[DIM + 2 * p + 1];
}

// ---------------- 7) cross-attention: one CTA per (head, frame) ----------------
// KV length = 32; warp-per-query-row, lane-per-key softmax.
__global__ void __launch_bounds__(256) attn_kernel() {
    const int h = blockIdx.x;    // 0..11
    const int t = blockIdx.y;    // 0..20
    __shared__ float ks[32][132];   // pad 132: conflict-free row-major float4 reads
    __shared__ float vs[32][128];
    __shared__ float qs[8][128];

    const int tid = threadIdx.x;
    // load K,V for this (t,h): rows t*32+a, cols h*128..h*128+127
    for (int i = tid; i < 32 * 128; i += 256) {
        int a = i >> 7, d = i & 127;
        size_t src = (size_t)(t * 32 + a) * DIM + h * HD + d;
        ks[a][d] = g_k[src];
        vs[a][d] = g_v[src];
    }
    __syncthreads();

    const int w = tid >> 5, l = tid & 31;
    const float4* vs4base = (const float4*)&vs[0][0];

    for (int s = w; s < S_SP; s += 8) {
        size_t rowoff = (size_t)(t * S_SP + s) * DIM + h * HD;
        // stage q row into smem (one float4 per lane)
        ((float4*)&qs[w][0])[l] = ((const float4*)(g_q + rowoff))[l];
        __syncwarp();

        // lane l owns key l: full 128-d dot product
        float acc = 0.0f;
        const float4* qr = (const float4*)&qs[w][0];
        const float4* kr = (const float4*)&ks[l][0];
#pragma unroll
        for (int j = 0; j < 32; j++) {
            float4 a4 = qr[j];
            float4 b4 = kr[j];
            acc += a4.x * b4.x + a4.y * b4.y + a4.z * b4.z + a4.w * b4.w;
        }
        acc *= 0.08838834764831845f;   // 1/sqrt(128)

        // softmax across the 32 lanes (keys)
        float mx = acc;
#pragma unroll
        for (int o = 16; o > 0; o >>= 1) mx = fmaxf(mx, __shfl_xor_sync(0xFFFFFFFFu, mx, o));
        float e = __expf(acc - mx);
        float sum = e;
#pragma unroll
        for (int o = 16; o > 0; o >>= 1) sum += __shfl_xor_sync(0xFFFFFFFFu, sum, o);
        float p = e / sum;

        // out[d] = sum_a p_a * v[a][d]; lane l covers d = 4l..4l+3
        float4 o4 = make_float4(0.f, 0.f, 0.f, 0.f);
#pragma unroll
        for (int a = 0; a < 32; a++) {
            float pa = __shfl_sync(0xFFFFFFFFu, p, a);
            float4 vv = vs4base[a * 32 + l];
            o4.x += pa * vv.x; o4.y += pa * vv.y; o4.z += pa * vv.z; o4.w += pa * vv.w;
        }
        ((float4*)(g_attn + rowoff))[l] = o4;
        __syncwarp();   // protect qs[w] before next iteration overwrites it
    }
}

// ---------------- launch ----------------
extern "C" void kernel_launch(void* const* d_in, const int* in_sizes, int n_in,
                              void* d_out, int out_size)
{
    const float* x    = (const float*)d_in[0];   // [1, 32760, 1536]
    const float* ehs  = (const float*)d_in[1];   // [21, 32, 768]
    const float* amap = (const float*)d_in[2];   // [2, 32760]
    const float* q_w  = (const float*)d_in[3];   // [1536, 1536]
    const float* q_b  = (const float*)d_in[4];
    const float* kv_w = (const float*)d_in[5];   // [3072, 768]
    const float* kv_b = (const float*)d_in[6];
    const float* p_w  = (const float*)d_in[7];   // [1536, 1536]
    const float* p_b  = (const float*)d_in[8];
    float* out = (float*)d_out;

    float *q, *attn, *kv;
    cudaGetSymbolAddress((void**)&q,    g_q);
    cudaGetSymbolAddress((void**)&attn, g_attn);
    cudaGetSymbolAddress((void**)&kv,   g_kv);

    // 1-2: routing positions
    minmax_kernel<<<1, 256>>>(amap);
    pos_kernel<<<(N_TOK + 255) / 256, 256>>>(amap);

    // 3: q = x @ q_w^T + q_b   [32760,1536]
    gemm_nt_bias<<<dim3(DIM / 128, (N_TOK + 127) / 128), 256>>>(x, q_w, q_b, q, N_TOK, DIM, DIM);

    // 4: RoPE(q)
    rope_q_kernel<<<(N_TOK * (DIM / 2) + 255) / 256, 256>>>();

    // 5: kv = ehs @ kv_w^T + kv_b   [672,3072]
    gemm_nt_bias<<<dim3((2 * DIM) / 128, (KV_ROWS + 127) / 128), 256>>>(ehs, kv_w, kv_b, kv, KV_ROWS, 2 * DIM, ENC);

    // 6: split + RoPE(k)
    rope_k_split_kernel<<<(KV_ROWS * (DIM / 2) + 255) / 256, 256>>>();

    // 7: cross-attention
    attn_kernel<<<dim3(NHEADS, N_T), 256>>>();

    // 8: out = attn @ proj_w^T + proj_b
    gemm_nt_bias<<<dim3(DIM / 128, (N_TOK + 127) / 128), 256>>>(attn, p_w, p_b, out, N_TOK, DIM, DIM);
}

// round 2
// speedup vs baseline: 3.2948x; 3.2948x over previous
#include <cuda_runtime.h>
#include <cstdint>
#include <math.h>

// ---------------- fixed problem shapes ----------------
#define N_TOK   32760          // N_t * N_h * N_w = 21*30*52
#define DIM     1536
#define NHEADS  12
#define HD      128
#define S_SP    1560           // 30*52
#define N_T     21
#define ENC     768
#define NA      32
#define KV_ROWS 672            // N_t * NA
#define LOG2_10000 13.287712379549449f

// ---------------- scratch (device globals; no runtime alloc) ----------------
__device__ float g_xtf[N_TOK * DIM];        // tf32-rounded x
__device__ float g_q[N_TOK * DIM];
__device__ float g_attn[N_TOK * DIM];       // tf32-rounded attention output
__device__ float g_kv[KV_ROWS * 2 * DIM];
__device__ float g_k[KV_ROWS * DIM];
__device__ float g_v[KV_ROWS * DIM];
__device__ float g_qwtf[DIM * DIM];         // tf32-rounded q_w
__device__ float g_pwtf[DIM * DIM];         // tf32-rounded proj_w
__device__ float g_pos[N_TOK];
__device__ float g_mm[4];                   // min0,max0,min1,max1

// ---------------- helpers ----------------
__device__ __forceinline__ uint32_t smem_u32(const void* p) {
    uint32_t r;
    asm("{.reg .u64 t; cvta.to.shared.u64 t, %1; cvt.u32.u64 %0, t;}" : "=r"(r) : "l"(p));
    return r;
}

__device__ __forceinline__ float tf32_rna(float x) {
    uint32_t u;
    asm("cvt.rna.tf32.f32 %0, %1;" : "=r"(u) : "f"(x));
    return __uint_as_float(u);
}

#define LDSM4(r0, r1, r2, r3, addr)                                            \
    asm volatile("ldmatrix.sync.aligned.m8n8.x4.shared.b16 {%0,%1,%2,%3}, [%4];" \
                 : "=r"(r0), "=r"(r1), "=r"(r2), "=r"(r3) : "r"(addr))

#define MMA_TF32(d, a, b0, b1)                                                 \
    asm volatile("mma.sync.aligned.m16n8k8.row.col.f32.tf32.tf32.f32 "          \
                 "{%0,%1,%2,%3},{%4,%5,%6,%7},{%8,%9},{%0,%1,%2,%3};"          \
                 : "+f"(d[0]), "+f"(d[1]), "+f"(d[2]), "+f"(d[3])              \
                 : "r"(a[0]), "r"(a[1]), "r"(a[2]), "r"(a[3]), "r"(b0), "r"(b1))

// ---------------- 0) tf32 RN rounding pass ----------------
__global__ void round_tf32_kernel(const float* __restrict__ in, float* __restrict__ out, int n4) {
    int i = blockIdx.x * blockDim.x + threadIdx.x;
    if (i >= n4) return;
    float4 v = ((const float4*)in)[i];
    v.x = tf32_rna(v.x); v.y = tf32_rna(v.y); v.z = tf32_rna(v.z); v.w = tf32_rna(v.w);
    ((float4*)out)[i] = v;
}

// ---------------- 1) min/max of the two attn-map rows ----------------
__global__ void minmax_kernel(const float* __restrict__ m) {
    __shared__ float s0[256], s1[256], s2[256], s3[256];
    int tid = threadIdx.x;
    float mn0 = 1e30f, mx0 = -1e30f, mn1 = 1e30f, mx1 = -1e30f;
    for (int i = tid; i < N_TOK; i += 256) {
        float v0 = m[i], v1 = m[N_TOK + i];
        mn0 = fminf(mn0, v0); mx0 = fmaxf(mx0, v0);
        mn1 = fminf(mn1, v1); mx1 = fmaxf(mx1, v1);
    }
    s0[tid] = mn0; s1[tid] = mx0; s2[tid] = mn1; s3[tid] = mx1;
    __syncthreads();
    for (int off = 128; off > 0; off >>= 1) {
        if (tid < off) {
            s0[tid] = fminf(s0[tid], s0[tid + off]);
            s1[tid] = fmaxf(s1[tid], s1[tid + off]);
            s2[tid] = fminf(s2[tid], s2[tid + off]);
            s3[tid] = fmaxf(s3[tid], s3[tid + off]);
        }
        __syncthreads();
    }
    if (tid == 0) { g_mm[0] = s0[0]; g_mm[1] = s1[0]; g_mm[2] = s2[0]; g_mm[3] = s3[0]; }
}

// ---------------- 2) per-token rotary position (speaker routing) ----------------
__global__ void pos_kernel(const float* __restrict__ m) {
    int n = blockIdx.x * blockDim.x + threadIdx.x;
    if (n >= N_TOK) return;
    float m0 = m[n], m1 = m[N_TOK + n];
    float r;
    if (m0 >= m1) {
        r = (m0 - g_mm[0]) / (g_mm[1] - g_mm[0] + 1e-8f) * 4.0f;
    } else {
        r = (m1 - g_mm[2]) / (g_mm[3] - g_mm[2] + 1e-8f) * 4.0f + 20.0f;
    }
    g_pos[n] = r;
}

// ---------------- tf32 tensor-core GEMM:  C[M,N] = A[M,K] * B[N,K]^T + bias[N] ----
// 128x128x32 CTA tile, 8 warps (2x4), warp tile 64x32, mma.m16n8k8.tf32,
// cp.async double-buffered smem with 128B XOR swizzle, ldmatrix.x4 fragments.
__device__ __forceinline__ void issue_tile(
    const float* A, const float* B, int M, int K,
    int row0, int col0, int kt, uint32_t sAbuf, uint32_t sBbuf,
    int ldrow, int ldchunk)
{
    const uint32_t doff = (uint32_t)ldrow * 128u + (((uint32_t)ldchunk * 16u) ^ (((uint32_t)ldrow & 7u) << 4));
    const float* ga = A + (size_t)(row0 + ldrow) * K + kt * 32 + ldchunk * 4;
    const float* gb = B + (size_t)(col0 + ldrow) * K + kt * 32 + ldchunk * 4;
#pragma unroll
    for (int p = 0; p < 4; p++) {
        int sz = ((row0 + ldrow + p * 32) < M) ? 16 : 0;
        asm volatile("cp.async.cg.shared.global [%0], [%1], 16, %2;"
                     :: "r"(sAbuf + doff + p * 32 * 128), "l"(ga + (size_t)p * 32 * K), "r"(sz));
        asm volatile("cp.async.cg.shared.global [%0], [%1], 16;"
                     :: "r"(sBbuf + doff + p * 32 * 128), "l"(gb + (size_t)p * 32 * K));
    }
    asm volatile("cp.async.commit_group;");
}

__global__ void __launch_bounds__(256, 2) gemm_tf32(
    const float* __restrict__ A, const float* __restrict__ B,
    const float* __restrict__ bias, float* __restrict__ C,
    int M, int N, int K)
{
    extern __shared__ float smem[];
    const int tid  = threadIdx.x;
    const int lane = tid & 31, warp = tid >> 5;
    const int wm = warp >> 2, wn = warp & 3;          // 2 x 4 warp grid
    const int row0 = blockIdx.y * 128, col0 = blockIdx.x * 128;
    const int ldrow = tid >> 3, ldchunk = tid & 7;

    const uint32_t sA = smem_u32(smem);
    const uint32_t sB = sA + 2 * 16384;
    const int ktiles = K >> 5;

    issue_tile(A, B, M, K, row0, col0, 0, sA, sB, ldrow, ldchunk);
    issue_tile(A, B, M, K, row0, col0, 1, sA + 16384, sB + 16384, ldrow, ldchunk);

    float acc[4][4][4];
#pragma unroll
    for (int i = 0; i < 4; i++)
#pragma unroll
        for (int j = 0; j < 4; j++)
#pragma unroll
            for (int k = 0; k < 4; k++) acc[i][j][k] = 0.0f;

    // ldmatrix per-thread addressing (lanes 0-7 -> mat0 rows, 8-15 -> mat1, ...)
    const int aRow = wm * 64 + ((lane >> 3) & 1) * 8 + (lane & 7);
    const int bRow = wn * 32 + ((lane >> 3) & 1) * 8 + (lane & 7);
    const uint32_t colSel = ((lane >> 4) & 1) * 16;
    const uint32_t xorv = ((uint32_t)lane & 7u) << 4;

    for (int it = 0; it < ktiles; it++) {
        if (it + 1 < ktiles) { asm volatile("cp.async.wait_group 1;"); }
        else                 { asm volatile("cp.async.wait_group 0;"); }
        __syncthreads();
        const uint32_t bA = sA + (it & 1) * 16384;
        const uint32_t bB = sB + (it & 1) * 16384;
#pragma unroll
        for (int ks = 0; ks < 4; ks++) {
            uint32_t a[4][4], bb[2][4];
            const uint32_t cb = ((uint32_t)(ks * 32) + colSel) ^ xorv;
#pragma unroll
            for (int mf = 0; mf < 4; mf++) {
                uint32_t ad = bA + (uint32_t)(aRow + mf * 16) * 128 + cb;
                LDSM4(a[mf][0], a[mf][1], a[mf][2], a[mf][3], ad);
            }
#pragma unroll
            for (int nh = 0; nh < 2; nh++) {
                uint32_t bd = bB + (uint32_t)(bRow + nh * 16) * 128 + cb;
                LDSM4(bb[nh][0], bb[nh][1], bb[nh][2], bb[nh][3], bd);
            }
#pragma unroll
            for (int mf = 0; mf < 4; mf++)
#pragma unroll
                for (int nf = 0; nf < 4; nf++) {
                    const int nh = nf >> 1, lo = nf & 1;
                    MMA_TF32(acc[mf][nf], a[mf], bb[nh][lo], bb[nh][2 + lo]);
                }
        }
        __syncthreads();
        if (it + 2 < ktiles)
            issue_tile(A, B, M, K, row0, col0, it + 2,
                       sA + (it & 1) * 16384, sB + (it & 1) * 16384, ldrow, ldchunk);
    }

    // epilogue: c0,c1 at (row=lane>>2, col=2*(lane&3)); c2,c3 at row+8
#pragma unroll
    for (int mf = 0; mf < 4; mf++) {
        const int r0 = row0 + wm * 64 + mf * 16 + (lane >> 2);
#pragma unroll
        for (int nf = 0; nf < 4; nf++) {
            const int c = col0 + wn * 32 + nf * 8 + (lane & 3) * 2;
            const float2 bv = *(const float2*)(bias + c);
            if (r0 < M) {
                float2 o = make_float2(acc[mf][nf][0] + bv.x, acc[mf][nf][1] + bv.y);
                *(float2*)(C + (size_t)r0 * N + c) = o;
            }
            if (r0 + 8 < M) {
                float2 o = make_float2(acc[mf][nf][2] + bv.x, acc[mf][nf][3] + bv.y);
                *(float2*)(C + (size_t)(r0 + 8) * N + c) = o;
            }
        }
    }
}

// ---------------- fp32 SIMT GEMM (kept for the small kv projection) ----------
__global__ void __launch_bounds__(256) gemm_nt_bias(
    const float* __restrict__ A, const float* __restrict__ B,
    const float* __restrict__ bias, float* __restrict__ C,
    int M, int N, int K)
{
    __shared__ float As[8][128];
    __shared__ float Bs[8][128];
    const int tid  = threadIdx.x;
    const int row0 = blockIdx.y * 128;
    const int col0 = blockIdx.x * 128;
    const int tx = tid & 15;
    const int ty = tid >> 4;
    const int lr = tid >> 1;
    const int lc = (tid & 1) * 4;

    float acc[8][8];
#pragma unroll
    for (int i = 0; i < 8; i++)
#pragma unroll
        for (int j = 0; j < 8; j++) acc[i][j] = 0.0f;

    const bool arow_ok = (row0 + lr) < M;
    const float* Ap = A + (size_t)(row0 + lr) * K + lc;
    const float* Bp = B + (size_t)(col0 + lr) * K + lc;

    for (int k0 = 0; k0 < K; k0 += 8) {
        float4 av = arow_ok ? *(const float4*)(Ap + k0) : make_float4(0.f, 0.f, 0.f, 0.f);
        float4 bv = *(const float4*)(Bp + k0);
        As[lc + 0][lr] = av.x; As[lc + 1][lr] = av.y; As[lc + 2][lr] = av.z; As[lc + 3][lr] = av.w;
        Bs[lc + 0][lr] = bv.x; Bs[lc + 1][lr] = bv.y; Bs[lc + 2][lr] = bv.z; Bs[lc + 3][lr] = bv.w;
        __syncthreads();
#pragma unroll
        for (int k = 0; k < 8; k++) {
            float a[8], b[8];
#pragma unroll
            for (int i = 0; i < 8; i++) a[i] = As[k][ty * 8 + i];
#pragma unroll
            for (int j = 0; j < 8; j++) b[j] = Bs[k][tx * 8 + j];
#pragma unroll
            for (int i = 0; i < 8; i++)
#pragma unroll
                for (int j = 0; j < 8; j++)
                    acc[i][j] += a[i] * b[j];
        }
        __syncthreads();
    }

#pragma unroll
    for (int i = 0; i < 8; i++) {
        int r = row0 + ty * 8 + i;
        if (r < M) {
            float* Cp = C + (size_t)r * N + col0 + tx * 8;
            const float* bp = bias + col0 + tx * 8;
#pragma unroll
            for (int j = 0; j < 8; j++)
                Cp[j] = acc[i][j] + bp[j];
        }
    }
}

// ---------------- 4) interleaved RoPE on q ----------------
__global__ void rope_q_kernel() {
    int idx = blockIdx.x * blockDim.x + threadIdx.x;
    if (idx >= N_TOK * (DIM / 2)) return;
    int n = idx / (DIM / 2);
    int p = idx - n * (DIM / 2);
    int i = p & 63;
    float fr = exp2f(-(float)i * (LOG2_10000 / 64.0f));
    float th = g_pos[n] * fr;
    float s, c;
    sincosf(th, &s, &c);
    float* base = g_q + (size_t)n * DIM + 2 * p;
    float a = base[0], b = base[1];
    base[0] = a * c - b * s;
    base[1] = b * c + a * s;
}

// ---------------- 6) split kv -> k (bucket-centre RoPE) and v ----------------
__global__ void rope_k_split_kernel() {
    int idx = blockIdx.x * blockDim.x + threadIdx.x;
    if (idx >= KV_ROWS * (DIM / 2)) return;
    int r = idx / (DIM / 2);
    int p = idx - r * (DIM / 2);
    int a = r & 31;
    float pos = (a < 16) ? 2.0f : 22.0f;
    int i = p & 63;
    float fr = exp2f(-(float)i * (LOG2_10000 / 64.0f));
    float th = pos * fr;
    float s, c;
    sincosf(th, &s, &c);
    const float* kvr = g_kv + (size_t)r * (2 * DIM);
    float ka = kvr[2 * p], kb = kvr[2 * p + 1];
    size_t o = (size_t)r * DIM + 2 * p;
    g_k[o]     = ka * c - kb * s;
    g_k[o + 1] = kb * c + ka * s;
    g_v[o]     = kvr[DIM + 2 * p];
    g_v[o + 1] = kvr[DIM + 2 * p + 1];
}

// ---------------- 7) cross-attention (KV len 32), tf32-rounded output -------
__global__ void __launch_bounds__(256) attn_kernel() {
    const int h = blockIdx.x;
    const int t = blockIdx.y;
    __shared__ float ks[32][132];
    __shared__ float vs[32][128];
    __shared__ float qs[8][128];

    const int tid = threadIdx.x;
    for (int i = tid; i < 32 * 128; i += 256) {
        int a = i >> 7, d = i & 127;
        size_t src = (size_t)(t * 32 + a) * DIM + h * HD + d;
        ks[a][d] = g_k[src];
        vs[a][d] = g_v[src];
    }
    __syncthreads();

    const int w = tid >> 5, l = tid & 31;
    const float4* vs4base = (const float4*)&vs[0][0];

    for (int s = w; s < S_SP; s += 8) {
        size_t rowoff = (size_t)(t * S_SP + s) * DIM + h * HD;
        ((float4*)&qs[w][0])[l] = ((const float4*)(g_q + rowoff))[l];
        __syncwarp();

        float acc = 0.0f;
        const float4* qr = (const float4*)&qs[w][0];
        const float4* kr = (const float4*)&ks[l][0];
#pragma unroll
        for (int j = 0; j < 32; j++) {
            float4 a4 = qr[j];
            float4 b4 = kr[j];
            acc += a4.x * b4.x + a4.y * b4.y + a4.z * b4.z + a4.w * b4.w;
        }
        acc *= 0.08838834764831845f;

        float mx = acc;
#pragma unroll
        for (int o = 16; o > 0; o >>= 1) mx = fmaxf(mx, __shfl_xor_sync(0xFFFFFFFFu, mx, o));
        float e = __expf(acc - mx);
        float sum = e;
#pragma unroll
        for (int o = 16; o > 0; o >>= 1) sum += __shfl_xor_sync(0xFFFFFFFFu, sum, o);
        float p = e / sum;

        float4 o4 = make_float4(0.f, 0.f, 0.f, 0.f);
#pragma unroll
        for (int a = 0; a < 32; a++) {
            float pa = __shfl_sync(0xFFFFFFFFu, p, a);
            float4 vv = vs4base[a * 32 + l];
            o4.x += pa * vv.x; o4.y += pa * vv.y; o4.z += pa * vv.z; o4.w += pa * vv.w;
        }
        // round to tf32 so the proj GEMM sees RN-rounded inputs
        o4.x = tf32_rna(o4.x); o4.y = tf32_rna(o4.y);
        o4.z = tf32_rna(o4.z); o4.w = tf32_rna(o4.w);
        ((float4*)(g_attn + rowoff))[l] = o4;
        __syncwarp();
    }
}

// ---------------- launch ----------------
extern "C" void kernel_launch(void* const* d_in, const int* in_sizes, int n_in,
                              void* d_out, int out_size)
{
    const float* x    = (const float*)d_in[0];
    const float* ehs  = (const float*)d_in[1];
    const float* amap = (const float*)d_in[2];
    const float* q_w  = (const float*)d_in[3];
    const float* q_b  = (const float*)d_in[4];
    const float* kv_w = (const float*)d_in[5];
    const float* kv_b = (const float*)d_in[6];
    const float* p_w  = (const float*)d_in[7];
    const float* p_b  = (const float*)d_in[8];
    float* out = (float*)d_out;

    float *xtf, *q, *attn, *kv, *qwtf, *pwtf;
    cudaGetSymbolAddress((void**)&xtf,  g_xtf);
    cudaGetSymbolAddress((void**)&q,    g_q);
    cudaGetSymbolAddress((void**)&attn, g_attn);
    cudaGetSymbolAddress((void**)&kv,   g_kv);
    cudaGetSymbolAddress((void**)&qwtf, g_qwtf);
    cudaGetSymbolAddress((void**)&pwtf, g_pwtf);

    static bool attr_set = false;
    cudaFuncSetAttribute(gemm_tf32, cudaFuncAttributeMaxDynamicSharedMemorySize, 65536);
    (void)attr_set;

    // 1-2: routing positions
    minmax_kernel<<<1, 256>>>(amap);
    pos_kernel<<<(N_TOK + 255) / 256, 256>>>(amap);

    // 0: tf32 RN pre-rounding of GEMM inputs
    {
        int n4x = (N_TOK * DIM) / 4;
        round_tf32_kernel<<<(n4x + 255) / 256, 256>>>(x, xtf, n4x);
        int n4w = (DIM * DIM) / 4;
        round_tf32_kernel<<<(n4w + 255) / 256, 256>>>(q_w, qwtf, n4w);
        round_tf32_kernel<<<(n4w + 255) / 256, 256>>>(p_w, pwtf, n4w);
    }

    // 3: q = x @ q_w^T + q_b   (tf32 tensor cores)
    gemm_tf32<<<dim3(DIM / 128, (N_TOK + 127) / 128), 256, 65536>>>(
        xtf, qwtf, q_b, q, N_TOK, DIM, DIM);

    // 4: RoPE(q)
    rope_q_kernel<<<(N_TOK * (DIM / 2) + 255) / 256, 256>>>();

    // 5: kv = ehs @ kv_w^T + kv_b  (small; fp32 keeps K/V exact)
    gemm_nt_bias<<<dim3((2 * DIM) / 128, (KV_ROWS + 127) / 128), 256>>>(
        ehs, kv_w, kv_b, kv, KV_ROWS, 2 * DIM, ENC);

    // 6: split + RoPE(k)
    rope_k_split_kernel<<<(KV_ROWS * (DIM / 2) + 255) / 256, 256>>>();

    // 7: cross-attention (rounds its output to tf32)
    attn_kernel<<<dim3(NHEADS, N_T), 256>>>();

    // 8: out = attn @ proj_w^T + proj_b  (tf32 tensor cores)
    gemm_tf32<<<dim3(DIM / 128, (N_TOK + 127) / 128), 256, 65536>>>(
        attn, pwtf, p_b, out, N_TOK, DIM, DIM);
}